// round 1
// baseline (speedup 1.0000x reference)
#include <cuda_runtime.h>
#include <cstdint>

// Problem constants
#define N_V   50000
#define R_    5
#define A_    8
#define RA    40
#define C_    64
#define T_    64
#define O_    8
#define KX    2560      // RA * C
#define KTOT  2624      // KX + C (center fold appended)
#define NCOL  512       // O * T

// Scratch (static device allocations are the sanctioned workaround — no cudaMalloc)
__device__ float g_X[(size_t)N_V * KTOT];        // 524.8 MB: interpolated features + appended center signal
__device__ float g_Bt[(size_t)KTOT * NCOL];      // 5.4 MB: effective weights, K-major (K x 512)
__device__ float g_biasExt[NCOL];

// ---------------------------------------------------------------------------
// K0: fold interpolation prior + rotation + center weights into B (K x 512)
//   Weff[o,t,m,c] = sum_{r,a} coeff[r,a,m] * W[t, r, (a+o)%A, c]
//   B[(m*64+c), j=o*64+t] = Weff ;  B[(2560+c), j] = cw[t,c] ; biasExt[j] = bias[t]
// ---------------------------------------------------------------------------
__global__ void build_B_kernel(const float* __restrict__ nw,
                               const float* __restrict__ cw,
                               const float* __restrict__ bias,
                               const float* __restrict__ coeff)
{
    int j = blockIdx.x;            // 0..511
    int o = j >> 6;
    int t = j & 63;
    int c = threadIdx.x;           // 64 threads

    __shared__ float s_coeff[R_ * A_ * RA];    // 1600 floats
    for (int i = c; i < R_ * A_ * RA; i += 64) s_coeff[i] = coeff[i];
    __syncthreads();

    // rotated weight values for this (t, c): wv[r][a] = W[t, r, (a+o)%A, c]
    float wv[R_][A_];
    #pragma unroll
    for (int r = 0; r < R_; r++)
        #pragma unroll
        for (int a = 0; a < A_; a++)
            wv[r][a] = nw[(((size_t)t * R_ + r) * A_ + ((a + o) & 7)) * C_ + c];

    for (int m = 0; m < RA; m++) {
        float acc = 0.f;
        #pragma unroll
        for (int r = 0; r < R_; r++)
            #pragma unroll
            for (int a = 0; a < A_; a++)
                acc += s_coeff[(r * A_ + a) * RA + m] * wv[r][a];
        g_Bt[(size_t)(m * C_ + c) * NCOL + j] = acc;
    }
    // center-weight fold (same for every o)
    g_Bt[(size_t)(KX + c) * NCOL + j] = cw[t * C_ + c];
    if (c == 0) g_biasExt[j] = bias[t];
}

// ---------------------------------------------------------------------------
// K1: build X: barycentric gather + interpolation, plus appended center signal.
//   X[n, m*64+c] = sum_j bw[n,m,j] * ms[idx[n,m,j], c]
//   X[n, 2560+c] = ms[n, c]
// One block per vertex, 256 threads (4 m-positions x 64 channels at a time).
// ---------------------------------------------------------------------------
__global__ void build_X_kernel(const float* __restrict__ ms,
                               const float* __restrict__ bary)
{
    int n   = blockIdx.x;
    int tid = threadIdx.x;

    __shared__ float sb[240];  // per-vertex bary block: 40 positions x 3 corners x (idx, w)
    const float* bn = bary + (size_t)n * 240;
    if (tid < 240) sb[tid] = bn[tid];
    __syncthreads();

    int g = tid >> 6;   // 0..3
    int c = tid & 63;
    float* Xn = g_X + (size_t)n * KTOT;

    #pragma unroll
    for (int mb = 0; mb < RA; mb += 4) {
        int m  = mb + g;
        int i0 = (int)sb[m * 6 + 0]; float w0 = sb[m * 6 + 1];
        int i1 = (int)sb[m * 6 + 2]; float w1 = sb[m * 6 + 3];
        int i2 = (int)sb[m * 6 + 4]; float w2 = sb[m * 6 + 5];
        Xn[m * C_ + c] = w0 * ms[(size_t)i0 * C_ + c]
                       + w1 * ms[(size_t)i1 * C_ + c]
                       + w2 * ms[(size_t)i2 * C_ + c];
    }
    if (g == 0) Xn[KX + c] = ms[(size_t)n * C_ + c];
}

// ---------------------------------------------------------------------------
// K2: SGEMM  out[n, j] = relu( biasExt[j] + sum_k X[n,k] * Bt[k,j] )
// 128x128 block tile, BK=8, 256 threads, 8x8 micro-tile per thread.
// ---------------------------------------------------------------------------
__global__ __launch_bounds__(256, 2)
void gemm_relu_kernel(float* __restrict__ out)
{
    const int BM = 128, BN = 128, BK = 8;

    __shared__ float As[BK][BM];   // A tile transposed (k-major)
    __shared__ float Bs[BK][BN];

    int tid = threadIdx.x;
    int m0 = blockIdx.y * BM;
    int n0 = blockIdx.x * BN;

    int tx = tid & 15;             // 16 cols of threads
    int ty = tid >> 4;             // 16 rows of threads

    float acc[8][8];
    #pragma unroll
    for (int i = 0; i < 8; i++)
        #pragma unroll
        for (int j = 0; j < 8; j++) acc[i][j] = 0.f;

    // A load mapping: thread -> one float4 of the 128x8 tile
    int aRow = tid >> 1;
    int aK   = (tid & 1) * 4;
    bool aValid = (m0 + aRow) < N_V;
    const float* Aptr = g_X + (size_t)(m0 + aRow) * KTOT + aK;

    // B load mapping: thread -> one float4 of the 8x128 tile
    int bK   = tid >> 5;           // 0..7
    int bCol = (tid & 31) * 4;
    const float* Bptr = g_Bt + (size_t)bK * NCOL + n0 + bCol;

    for (int k0 = 0; k0 < KTOT; k0 += BK) {
        float4 av = aValid ? *(const float4*)(Aptr + k0) : make_float4(0.f, 0.f, 0.f, 0.f);
        As[aK + 0][aRow] = av.x;
        As[aK + 1][aRow] = av.y;
        As[aK + 2][aRow] = av.z;
        As[aK + 3][aRow] = av.w;

        float4 bv = *(const float4*)(Bptr + (size_t)k0 * NCOL);
        *(float4*)&Bs[bK][bCol] = bv;

        __syncthreads();

        #pragma unroll
        for (int kk = 0; kk < BK; kk++) {
            float ra[8], rb[8];
            #pragma unroll
            for (int i = 0; i < 8; i++) ra[i] = As[kk][ty * 8 + i];
            #pragma unroll
            for (int j = 0; j < 8; j++) rb[j] = Bs[kk][tx * 8 + j];
            #pragma unroll
            for (int i = 0; i < 8; i++)
                #pragma unroll
                for (int j = 0; j < 8; j++)
                    acc[i][j] = fmaf(ra[i], rb[j], acc[i][j]);
        }
        __syncthreads();
    }

    // epilogue: bias + relu
    float bv[8];
    #pragma unroll
    for (int j = 0; j < 8; j++) bv[j] = g_biasExt[n0 + tx * 8 + j];

    #pragma unroll
    for (int i = 0; i < 8; i++) {
        int row = m0 + ty * 8 + i;
        if (row >= N_V) continue;
        float* orow = out + (size_t)row * NCOL + n0 + tx * 8;
        #pragma unroll
        for (int j = 0; j < 8; j++) {
            float v = acc[i][j] + bv[j];
            orow[j] = v > 0.f ? v : 0.f;
        }
    }
}

// ---------------------------------------------------------------------------
// Launch
// Inputs (metadata order): mesh_signal, bary_coordinates, neighbor_weights,
//                          center_weights, bias, interp_coeff
// ---------------------------------------------------------------------------
extern "C" void kernel_launch(void* const* d_in, const int* in_sizes, int n_in,
                              void* d_out, int out_size)
{
    const float* ms    = (const float*)d_in[0];
    const float* bary  = (const float*)d_in[1];
    const float* nw    = (const float*)d_in[2];
    const float* cw    = (const float*)d_in[3];
    const float* bias  = (const float*)d_in[4];
    const float* coeff = (const float*)d_in[5];
    float* out = (float*)d_out;

    build_B_kernel<<<NCOL, 64>>>(nw, cw, bias, coeff);
    build_X_kernel<<<N_V, 256>>>(ms, bary);

    dim3 grid(NCOL / 128, (N_V + 127) / 128);
    gemm_relu_kernel<<<grid, 256>>>(out);
}

// round 2
// speedup vs baseline: 3.0766x; 3.0766x over previous
#include <cuda_runtime.h>
#include <cstdint>

// Problem constants
#define N_V   50000
#define R_    5
#define A_    8
#define RA    40
#define C_    64
#define KX    2560            // RA * C
#define KTOT  2624            // KX + C (center fold appended)
#define NCOL  512             // O * T
#define KT_N  82              // KTOT / 32
#define MB_N  391             // ceil(50048 / 128)

// Scratch (static device arrays — no cudaMalloc allowed)
// A in MMA-fragment layout: per (row-tile mb of 128, k-tile kt of 32): 4096 floats.
__device__ float g_Afrag[(size_t)MB_N * KT_N * 4096];   // ~513 MB
// B in MMA-fragment layout: per (col-tile nb of 128, k-tile kt): 4096 floats.
__device__ float g_Bfrag[(size_t)4 * KT_N * 4096];      // 5.4 MB
__device__ float g_biasExt[NCOL];

__device__ __forceinline__ float tf32r(float x) {
    uint32_t u;
    asm("cvt.rna.tf32.f32 %0, %1;" : "=r"(u) : "f"(x));
    return __uint_as_float(u);
}

// ---------------------------------------------------------------------------
// K0: fold interpolation prior + rotation + center weights into B-fragments.
//   Weff[o,t,m,c] = sum_{r,a} coeff[r,a,m] * W[t, r, (a+o)%A, c]
//   column j = o*64+t ; row k = m*64+c (neighbor) or 2560+c (center)
// B fragment layout within a (nb, kt) 16KB tile:
//   idx = ((NT*4+kk)*32 + gn*4 + t4)*2 + r
//   where NT=(j%128)>>3, gn=(j%128)&7, kk=(k%32)>>3, t4=k&3, r=((k%32)&7)>=4
// ---------------------------------------------------------------------------
__device__ __forceinline__ size_t bfrag_addr(int k, int j) {
    int kt = k >> 5, kl = k & 31;
    int kk = kl >> 3, wi = kl & 7, t4 = wi & 3, r = wi >> 2;
    int nb = j >> 7, nl = j & 127;
    int NT = nl >> 3, gn = nl & 7;
    return ((size_t)(nb * KT_N + kt)) * 4096 +
           (size_t)(((NT * 4 + kk) * 32 + gn * 4 + t4) * 2 + r);
}

__global__ void build_B_kernel(const float* __restrict__ nw,
                               const float* __restrict__ cw,
                               const float* __restrict__ bias,
                               const float* __restrict__ coeff)
{
    int j = blockIdx.x;            // 0..511
    int o = j >> 6;
    int t = j & 63;
    int c = threadIdx.x;           // 64 threads

    __shared__ float s_coeff[R_ * A_ * RA];    // 1600 floats
    for (int i = c; i < R_ * A_ * RA; i += 64) s_coeff[i] = coeff[i];
    __syncthreads();

    float wv[R_][A_];
    #pragma unroll
    for (int r = 0; r < R_; r++)
        #pragma unroll
        for (int a = 0; a < A_; a++)
            wv[r][a] = nw[(((size_t)t * R_ + r) * A_ + ((a + o) & 7)) * C_ + c];

    for (int m = 0; m < RA; m++) {
        float acc = 0.f;
        #pragma unroll
        for (int r = 0; r < R_; r++)
            #pragma unroll
            for (int a = 0; a < A_; a++)
                acc += s_coeff[(r * A_ + a) * RA + m] * wv[r][a];
        g_Bfrag[bfrag_addr(m * C_ + c, j)] = tf32r(acc);
    }
    g_Bfrag[bfrag_addr(KX + c, j)] = tf32r(cw[t * C_ + c]);
    if (c == 0) g_biasExt[j] = bias[t];
}

// ---------------------------------------------------------------------------
// K1: barycentric gather + interpolation, written directly as A-fragments.
// One block per vertex PAIR (n, n+8) so each 16B fragment
//   (a0,a2,a1,a3) = (row g @k, row g @k+4, row g+8 @k, row g+8 @k+4)
// is written densely as one float4.
// ---------------------------------------------------------------------------
__global__ __launch_bounds__(256)
void build_X_kernel(const float* __restrict__ ms,
                    const float* __restrict__ bary)
{
    int bp = blockIdx.x;           // 0 .. MB_N*64-1
    int mb = bp >> 6;
    int q  = bp & 63;
    int MT = q >> 3;               // 0..7 (16-row tile within 128-row block)
    int gl = q & 7;                // 0..7 (low row within 16-row tile)
    int n0 = mb * 128 + MT * 16 + gl;

    __shared__ float s_row[2][KTOT];
    __shared__ float sb[240];
    int tid = threadIdx.x;

    #pragma unroll
    for (int v = 0; v < 2; v++) {
        int n = n0 + 8 * v;
        if (n < N_V) {
            if (tid < 240) sb[tid] = bary[(size_t)n * 240 + tid];
            __syncthreads();
            int g4 = tid >> 6;     // 0..3
            int c  = tid & 63;
            #pragma unroll
            for (int it = 0; it < 10; it++) {
                int m  = it * 4 + g4;
                int i0 = (int)sb[m * 6 + 0]; float w0 = sb[m * 6 + 1];
                int i1 = (int)sb[m * 6 + 2]; float w1 = sb[m * 6 + 3];
                int i2 = (int)sb[m * 6 + 4]; float w2 = sb[m * 6 + 5];
                s_row[v][m * C_ + c] = w0 * ms[(size_t)i0 * C_ + c]
                                     + w1 * ms[(size_t)i1 * C_ + c]
                                     + w2 * ms[(size_t)i2 * C_ + c];
            }
            if (g4 == 0) s_row[v][KX + c] = ms[(size_t)n * C_ + c];
        } else {
            for (int i = tid; i < KTOT; i += 256) s_row[v][i] = 0.f;
        }
        __syncthreads();
    }

    // write fragments: 82 kt-tiles x 16 (kk,t4) float4s = 1312 float4
    for (int w = tid; w < KT_N * 16; w += 256) {
        int kt = w >> 4;
        int kk = (w >> 2) & 3;
        int t4 = w & 3;
        int k  = kt * 32 + kk * 8 + t4;
        float4 val = make_float4(tf32r(s_row[0][k]), tf32r(s_row[0][k + 4]),
                                 tf32r(s_row[1][k]), tf32r(s_row[1][k + 4]));
        ((float4*)(g_Afrag + ((size_t)mb * KT_N + kt) * 4096))
            [(MT * 4 + kk) * 32 + gl * 4 + t4] = val;
    }
}

// ---------------------------------------------------------------------------
// K2: tf32 tensor-core GEMM + bias + relu.
//   out[n, j] = relu( biasExt[j] + sum_k X[n,k] * B[k,j] )
// 128x128x32 tiles, 256 threads = 8 warps (2 m x 4 n), m16n8k8 tf32 mma.
// ---------------------------------------------------------------------------
__device__ __forceinline__ void mma_tf32(float* c, float a0, float a1, float a2, float a3,
                                         float b0, float b1)
{
    asm volatile(
        "mma.sync.aligned.m16n8k8.row.col.f32.tf32.tf32.f32 "
        "{%0,%1,%2,%3}, {%4,%5,%6,%7}, {%8,%9}, {%0,%1,%2,%3};\n"
        : "+f"(c[0]), "+f"(c[1]), "+f"(c[2]), "+f"(c[3])
        : "r"(__float_as_uint(a0)), "r"(__float_as_uint(a1)),
          "r"(__float_as_uint(a2)), "r"(__float_as_uint(a3)),
          "r"(__float_as_uint(b0)), "r"(__float_as_uint(b1)));
}

__global__ __launch_bounds__(256)
void gemm_relu_kernel(float* __restrict__ out)
{
    __shared__ float As[2][4096];
    __shared__ float Bs[2][4096];

    int tid  = threadIdx.x;
    int warp = tid >> 5;
    int ln   = tid & 31;
    int wm   = warp >> 2;          // 0..1
    int wn   = warp & 3;           // 0..3
    int mb   = blockIdx.y;
    int nb   = blockIdx.x;

    const float4* Ag = (const float4*)(g_Afrag + (size_t)mb * KT_N * 4096);
    const float4* Bg = (const float4*)(g_Bfrag + (size_t)nb * KT_N * 4096);

    // prologue: load tile 0
    float4 pa[4], pb[4];
    #pragma unroll
    for (int i = 0; i < 4; i++) { pa[i] = Ag[tid + i * 256]; pb[i] = Bg[tid + i * 256]; }
    #pragma unroll
    for (int i = 0; i < 4; i++) {
        ((float4*)As[0])[tid + i * 256] = pa[i];
        ((float4*)Bs[0])[tid + i * 256] = pb[i];
    }
    __syncthreads();

    float acc[4][4][4];
    #pragma unroll
    for (int mt = 0; mt < 4; mt++)
        #pragma unroll
        for (int nt = 0; nt < 4; nt++)
            #pragma unroll
            for (int i = 0; i < 4; i++) acc[mt][nt][i] = 0.f;

    for (int kt = 0; kt < KT_N; kt++) {
        int cur = kt & 1;
        if (kt < KT_N - 1) {
            const float4* Agn = Ag + (kt + 1) * 1024;
            const float4* Bgn = Bg + (kt + 1) * 1024;
            #pragma unroll
            for (int i = 0; i < 4; i++) { pa[i] = Agn[tid + i * 256]; pb[i] = Bgn[tid + i * 256]; }
        }

        #pragma unroll
        for (int kk = 0; kk < 4; kk++) {
            float4 af[4];
            float2 bf[4];
            #pragma unroll
            for (int mt = 0; mt < 4; mt++)
                af[mt] = *(const float4*)&As[cur][(((wm * 4 + mt) * 4 + kk) * 32 + ln) * 4];
            #pragma unroll
            for (int nt = 0; nt < 4; nt++)
                bf[nt] = *(const float2*)&Bs[cur][(((wn * 4 + nt) * 4 + kk) * 32 + ln) * 2];
            #pragma unroll
            for (int mt = 0; mt < 4; mt++)
                #pragma unroll
                for (int nt = 0; nt < 4; nt++)
                    // frag float4 = (a0, a2, a1, a3)
                    mma_tf32(acc[mt][nt], af[mt].x, af[mt].z, af[mt].y, af[mt].w,
                             bf[nt].x, bf[nt].y);
        }

        if (kt < KT_N - 1) {
            int nxt = cur ^ 1;
            #pragma unroll
            for (int i = 0; i < 4; i++) {
                ((float4*)As[nxt])[tid + i * 256] = pa[i];
                ((float4*)Bs[nxt])[tid + i * 256] = pb[i];
            }
            __syncthreads();
        }
    }

    // epilogue: bias + relu, D fragment mapping
    int g  = ln >> 2;
    int t4 = ln & 3;
    #pragma unroll
    for (int nt = 0; nt < 4; nt++) {
        int col = nb * 128 + wn * 32 + nt * 8 + t4 * 2;
        float b0 = g_biasExt[col];
        float b1 = g_biasExt[col + 1];
        #pragma unroll
        for (int mt = 0; mt < 4; mt++) {
            int row0 = mb * 128 + wm * 64 + mt * 16 + g;
            float v0 = acc[mt][nt][0] + b0;
            float v1 = acc[mt][nt][1] + b1;
            float v2 = acc[mt][nt][2] + b0;
            float v3 = acc[mt][nt][3] + b1;
            v0 = v0 > 0.f ? v0 : 0.f;
            v1 = v1 > 0.f ? v1 : 0.f;
            v2 = v2 > 0.f ? v2 : 0.f;
            v3 = v3 > 0.f ? v3 : 0.f;
            if (row0 < N_V)
                *(float2*)(out + (size_t)row0 * NCOL + col) = make_float2(v0, v1);
            if (row0 + 8 < N_V)
                *(float2*)(out + (size_t)(row0 + 8) * NCOL + col) = make_float2(v2, v3);
        }
    }
}

// ---------------------------------------------------------------------------
// Launch
// Inputs: mesh_signal, bary_coordinates, neighbor_weights, center_weights,
//         bias, interp_coeff
// ---------------------------------------------------------------------------
extern "C" void kernel_launch(void* const* d_in, const int* in_sizes, int n_in,
                              void* d_out, int out_size)
{
    const float* ms    = (const float*)d_in[0];
    const float* bary  = (const float*)d_in[1];
    const float* nw    = (const float*)d_in[2];
    const float* cw    = (const float*)d_in[3];
    const float* bias  = (const float*)d_in[4];
    const float* coeff = (const float*)d_in[5];
    float* out = (float*)d_out;

    build_B_kernel<<<NCOL, 64>>>(nw, cw, bias, coeff);
    build_X_kernel<<<MB_N * 64, 256>>>(ms, bary);

    dim3 grid(4, MB_N);
    gemm_relu_kernel<<<grid, 256>>>(out);
}

// round 4
// speedup vs baseline: 3.5455x; 1.1524x over previous
#include <cuda_runtime.h>
#include <cstdint>

// Problem constants
#define N_V   50000
#define R_    5
#define A_    8
#define RA    40
#define C_    64
#define KX    2560            // RA * C
#define KTOT  2624            // KX + C (center fold appended)
#define NCOL  512             // O * T
#define KT_N  82              // KTOT / 32
#define MB_N  391             // ceil(50048 / 128)

// Scratch (static device arrays — no cudaMalloc allowed)
// A in MMA-fragment layout: per (row-tile mb of 128, k-tile kt of 32): 4096 floats.
__device__ float g_Afrag[(size_t)MB_N * KT_N * 4096];   // ~513 MB
// B in MMA-fragment layout: per (col-tile nb of 128, k-tile kt): 4096 floats.
__device__ float g_Bfrag[(size_t)4 * KT_N * 4096];      // 5.4 MB
__device__ float g_biasExt[NCOL];

__device__ __forceinline__ float tf32r(float x) {
    uint32_t u;
    asm("cvt.rna.tf32.f32 %0, %1;" : "=r"(u) : "f"(x));
    return __uint_as_float(u);
}

__device__ __forceinline__ uint32_t smem_u32(const void* p) {
    uint32_t a;
    asm("{ .reg .u64 t; cvta.to.shared.u64 t, %1; cvt.u32.u64 %0, t; }" : "=r"(a) : "l"(p));
    return a;
}

// ---------------------------------------------------------------------------
// K0: fold interpolation prior + rotation + center weights into B-fragments.
//   Weff[o,t,m,c] = sum_{r,a} coeff[r,a,m] * W[t, r, (a+o)%A, c]
// B fragment layout within a (nb, kt) 16KB tile:
//   idx = ((NT*4+kk)*32 + lane)*2 + r
// ---------------------------------------------------------------------------
__device__ __forceinline__ size_t bfrag_addr(int k, int j) {
    int kt = k >> 5, kl = k & 31;
    int kk = kl >> 3, wi = kl & 7, t4 = wi & 3, r = wi >> 2;
    int nb = j >> 7, nl = j & 127;
    int NT = nl >> 3, gn = nl & 7;
    return ((size_t)(nb * KT_N + kt)) * 4096 +
           (size_t)(((NT * 4 + kk) * 32 + gn * 4 + t4) * 2 + r);
}

__global__ void build_B_kernel(const float* __restrict__ nw,
                               const float* __restrict__ cw,
                               const float* __restrict__ bias,
                               const float* __restrict__ coeff)
{
    int j = blockIdx.x;            // 0..511
    int o = j >> 6;
    int t = j & 63;
    int c = threadIdx.x;           // 64 threads

    __shared__ float s_coeff[R_ * A_ * RA];
    for (int i = c; i < R_ * A_ * RA; i += 64) s_coeff[i] = coeff[i];
    __syncthreads();

    float wv[R_][A_];
    #pragma unroll
    for (int r = 0; r < R_; r++)
        #pragma unroll
        for (int a = 0; a < A_; a++)
            wv[r][a] = nw[(((size_t)t * R_ + r) * A_ + ((a + o) & 7)) * C_ + c];

    for (int m = 0; m < RA; m++) {
        float acc = 0.f;
        #pragma unroll
        for (int r = 0; r < R_; r++)
            #pragma unroll
            for (int a = 0; a < A_; a++)
                acc += s_coeff[(r * A_ + a) * RA + m] * wv[r][a];
        g_Bfrag[bfrag_addr(m * C_ + c, j)] = tf32r(acc);
    }
    g_Bfrag[bfrag_addr(KX + c, j)] = tf32r(cw[t * C_ + c]);
    if (c == 0) g_biasExt[j] = bias[t];
}

// ---------------------------------------------------------------------------
// K1: barycentric gather + interpolation, written directly as A-fragments.
// One block per vertex PAIR (n, n+8).
// ---------------------------------------------------------------------------
__global__ __launch_bounds__(256)
void build_X_kernel(const float* __restrict__ ms,
                    const float* __restrict__ bary)
{
    int bp = blockIdx.x;
    int mb = bp >> 6;
    int q  = bp & 63;
    int MT = q >> 3;
    int gl = q & 7;
    int n0 = mb * 128 + MT * 16 + gl;

    __shared__ float s_row[2][KTOT];
    __shared__ float sb[240];
    int tid = threadIdx.x;

    #pragma unroll
    for (int v = 0; v < 2; v++) {
        int n = n0 + 8 * v;
        if (n < N_V) {
            if (tid < 240) sb[tid] = bary[(size_t)n * 240 + tid];
            __syncthreads();
            int g4 = tid >> 6;
            int c  = tid & 63;
            #pragma unroll
            for (int it = 0; it < 10; it++) {
                int m  = it * 4 + g4;
                int i0 = (int)sb[m * 6 + 0]; float w0 = sb[m * 6 + 1];
                int i1 = (int)sb[m * 6 + 2]; float w1 = sb[m * 6 + 3];
                int i2 = (int)sb[m * 6 + 4]; float w2 = sb[m * 6 + 5];
                s_row[v][m * C_ + c] = w0 * ms[(size_t)i0 * C_ + c]
                                     + w1 * ms[(size_t)i1 * C_ + c]
                                     + w2 * ms[(size_t)i2 * C_ + c];
            }
            if (g4 == 0) s_row[v][KX + c] = ms[(size_t)n * C_ + c];
        } else {
            for (int i = tid; i < KTOT; i += 256) s_row[v][i] = 0.f;
        }
        __syncthreads();
    }

    for (int w = tid; w < KT_N * 16; w += 256) {
        int kt = w >> 4;
        int kk = (w >> 2) & 3;
        int t4 = w & 3;
        int k  = kt * 32 + kk * 8 + t4;
        float4 val = make_float4(tf32r(s_row[0][k]), tf32r(s_row[0][k + 4]),
                                 tf32r(s_row[1][k]), tf32r(s_row[1][k + 4]));
        ((float4*)(g_Afrag + ((size_t)mb * KT_N + kt) * 4096))
            [(MT * 4 + kk) * 32 + gl * 4 + t4] = val;
    }
}

// ---------------------------------------------------------------------------
// K2: tf32 mma.sync GEMM + bias + relu.
// BM=128, BN=256, BK=32. 256 threads = 8 warps (2m x 4n), warp tile 64x64.
// 3-stage cp.async pipeline. Fragment-layout tiles -> linear fills.
// ---------------------------------------------------------------------------
__device__ __forceinline__ void mma_tf32(float* c, float a0, float a1, float a2, float a3,
                                         float b0, float b1)
{
    asm volatile(
        "mma.sync.aligned.m16n8k8.row.col.f32.tf32.tf32.f32 "
        "{%0,%1,%2,%3}, {%4,%5,%6,%7}, {%8,%9}, {%0,%1,%2,%3};\n"
        : "+f"(c[0]), "+f"(c[1]), "+f"(c[2]), "+f"(c[3])
        : "r"(__float_as_uint(a0)), "r"(__float_as_uint(a1)),
          "r"(__float_as_uint(a2)), "r"(__float_as_uint(a3)),
          "r"(__float_as_uint(b0)), "r"(__float_as_uint(b1)));
}

__device__ __forceinline__ void cp16(uint32_t s, const void* g) {
    asm volatile("cp.async.cg.shared.global [%0], [%1], 16;" :: "r"(s), "l"(g));
}

#define STAGE_BYTES 49152      // 16KB A + 32KB B
#define SMEM_TOTAL  (3 * STAGE_BYTES)

__global__ __launch_bounds__(256)
void gemm_relu_kernel(float* __restrict__ out)
{
    extern __shared__ float smemf[];
    uint32_t sbase = smem_u32(smemf);

    int tid  = threadIdx.x;
    int warp = tid >> 5;
    int ln   = tid & 31;
    int wm   = warp >> 2;          // 0..1  (m half, 64 rows)
    int wn   = warp & 3;           // 0..3  (n quarter, 64 cols)
    int mb   = blockIdx.y;
    int bx   = blockIdx.x;         // 0..1  (n half of 256)

    const float* Ag  = g_Afrag + (size_t)mb * KT_N * 4096;
    const float* Bg0 = g_Bfrag + (size_t)(bx * 2 + 0) * KT_N * 4096;
    const float* Bg1 = g_Bfrag + (size_t)(bx * 2 + 1) * KT_N * 4096;

    auto issue = [&](int s) {
        uint32_t dst = sbase + (uint32_t)(s % 3) * STAGE_BYTES;
        const float* As = Ag + (size_t)s * 4096;
        #pragma unroll
        for (int i = 0; i < 4; i++)
            cp16(dst + (tid + i * 256) * 16, As + (tid + i * 256) * 4);
        const float* Bs0 = Bg0 + (size_t)s * 4096;
        const float* Bs1 = Bg1 + (size_t)s * 4096;
        #pragma unroll
        for (int i = 0; i < 4; i++)
            cp16(dst + 16384 + (tid + i * 256) * 16, Bs0 + (tid + i * 256) * 4);
        #pragma unroll
        for (int i = 0; i < 4; i++)
            cp16(dst + 32768 + (tid + i * 256) * 16, Bs1 + (tid + i * 256) * 4);
    };

    issue(0);
    asm volatile("cp.async.commit_group;" ::: "memory");
    issue(1);
    asm volatile("cp.async.commit_group;" ::: "memory");

    float acc[4][8][4];
    #pragma unroll
    for (int mt = 0; mt < 4; mt++)
        #pragma unroll
        for (int nt = 0; nt < 8; nt++)
            #pragma unroll
            for (int i = 0; i < 4; i++) acc[mt][nt][i] = 0.f;

    for (int kt = 0; kt < KT_N; kt++) {
        asm volatile("cp.async.wait_group 1;" ::: "memory");
        __syncthreads();

        if (kt + 2 < KT_N) issue(kt + 2);
        asm volatile("cp.async.commit_group;" ::: "memory");

        uint32_t bufA = sbase + (uint32_t)(kt % 3) * STAGE_BYTES;
        uint32_t bufB = bufA + 16384 + (uint32_t)(wn >> 1) * 16384;

        #pragma unroll
        for (int kk = 0; kk < 4; kk++) {
            float4 af[4];
            float2 bf[8];
            #pragma unroll
            for (int mt = 0; mt < 4; mt++) {
                uint32_t a = bufA + ((((wm * 4 + mt) * 4 + kk) * 32 + ln) * 16);
                asm volatile("ld.shared.v4.f32 {%0,%1,%2,%3}, [%4];"
                             : "=f"(af[mt].x), "=f"(af[mt].y), "=f"(af[mt].z), "=f"(af[mt].w)
                             : "r"(a));
            }
            #pragma unroll
            for (int nt = 0; nt < 8; nt++) {
                uint32_t b = bufB + (((((wn & 1) * 8 + nt) * 4 + kk) * 32 + ln) * 8);
                asm volatile("ld.shared.v2.f32 {%0,%1}, [%2];"
                             : "=f"(bf[nt].x), "=f"(bf[nt].y) : "r"(b));
            }
            #pragma unroll
            for (int mt = 0; mt < 4; mt++)
                #pragma unroll
                for (int nt = 0; nt < 8; nt++)
                    // frag float4 = (a0, a2, a1, a3)
                    mma_tf32(acc[mt][nt], af[mt].x, af[mt].z, af[mt].y, af[mt].w,
                             bf[nt].x, bf[nt].y);
        }
        __syncthreads();
    }

    // epilogue: bias + relu
    int g  = ln >> 2;
    int t4 = ln & 3;
    #pragma unroll
    for (int nt = 0; nt < 8; nt++) {
        int col = bx * 256 + wn * 64 + nt * 8 + t4 * 2;
        float b0 = g_biasExt[col];
        float b1 = g_biasExt[col + 1];
        #pragma unroll
        for (int mt = 0; mt < 4; mt++) {
            int row0 = mb * 128 + wm * 64 + mt * 16 + g;
            float v0 = acc[mt][nt][0] + b0;
            float v1 = acc[mt][nt][1] + b1;
            float v2 = acc[mt][nt][2] + b0;
            float v3 = acc[mt][nt][3] + b1;
            v0 = v0 > 0.f ? v0 : 0.f;
            v1 = v1 > 0.f ? v1 : 0.f;
            v2 = v2 > 0.f ? v2 : 0.f;
            v3 = v3 > 0.f ? v3 : 0.f;
            if (row0 < N_V)
                *(float2*)(out + (size_t)row0 * NCOL + col) = make_float2(v0, v1);
            if (row0 + 8 < N_V)
                *(float2*)(out + (size_t)(row0 + 8) * NCOL + col) = make_float2(v2, v3);
        }
    }
}

// ---------------------------------------------------------------------------
// Launch
// Inputs: mesh_signal, bary_coordinates, neighbor_weights, center_weights,
//         bias, interp_coeff
// ---------------------------------------------------------------------------
extern "C" void kernel_launch(void* const* d_in, const int* in_sizes, int n_in,
                              void* d_out, int out_size)
{
    const float* ms    = (const float*)d_in[0];
    const float* bary  = (const float*)d_in[1];
    const float* nw    = (const float*)d_in[2];
    const float* cw    = (const float*)d_in[3];
    const float* bias  = (const float*)d_in[4];
    const float* coeff = (const float*)d_in[5];
    float* out = (float*)d_out;

    cudaFuncSetAttribute(gemm_relu_kernel,
                         cudaFuncAttributeMaxDynamicSharedMemorySize, SMEM_TOTAL);

    build_B_kernel<<<NCOL, 64>>>(nw, cw, bias, coeff);
    build_X_kernel<<<MB_N * 64, 256>>>(ms, bary);

    dim3 grid(2, MB_N);
    gemm_relu_kernel<<<grid, 256, SMEM_TOTAL>>>(out);
}